// round 15
// baseline (speedup 1.0000x reference)
#include <cuda_runtime.h>
#include <cuda_fp16.h>
#include <stdint.h>
#include <math.h>

// Problem constants
#define BATCH 4
#define SEQ   2048
#define DIM   1024
#define MTOT  (BATCH * SEQ)      // 8192
#define BETA  0.03125f
#define BLOG2E 0.04508422f       // BETA * log2(e)

// GEMM tiling: 256x128 CTA tile, 8 warps (4x2 of 64x64), K-chunk 32, 80B rows
#define KC       32
#define RSTRIDE  80                  // bytes per smem row (32 fp16 + 16B pad)
#define TILE_A   (256 * RSTRIDE)     // 20480 B (A: 256 rows)
#define TILE_BB  (128 * RSTRIDE)     // 10240 B (B: 128 rows)
#define STAGE_B  (TILE_A + TILE_BB)  // 30720 B
#define NSTAGE   3
#define SMEM_TOTAL (NSTAGE * STAGE_B)  // 92160 B -> 1 CTA/SM (reg-bound anyway)

// ---------------------------------------------------------------------------
// Scratch (__device__ globals; allocation-free rule)
// ---------------------------------------------------------------------------
__device__ __align__(16) __half g_x[3 * MTOT * DIM];      // fp16 inputs
__device__ __align__(16) __half g_w[3 * DIM * DIM];       // fp16 weights (transposed)
__device__ __align__(16) float  g_bias[3 * DIM];
__device__ __align__(16) __half g_qkv[3 * MTOT * DIM];    // fp16 q,k,v
__device__ __align__(16) __half g_vt[MTOT * DIM];         // v transposed [z][D][S]
__device__ __align__(16) __half g_p[(size_t)BATCH * SEQ * SEQ];  // exp(beta*s)
__device__ __align__(16) float  g_rsum[MTOT];             // row sums (atomic)

// ---------------------------------------------------------------------------
// Helpers
// ---------------------------------------------------------------------------
__device__ __forceinline__ uint32_t s2u(const void* p) {
    return (uint32_t)__cvta_generic_to_shared(p);
}
__device__ __forceinline__ void cp16(uint32_t s, const void* g) {
    asm volatile("cp.async.cg.shared.global [%0], [%1], 16;" :: "r"(s), "l"(g));
}

#define LDSM4(r, addr)                                                        \
    asm volatile("ldmatrix.sync.aligned.m8n8.x4.shared.b16 {%0,%1,%2,%3}, [%4];" \
                 : "=r"((r)[0]), "=r"((r)[1]), "=r"((r)[2]), "=r"((r)[3])     \
                 : "r"(addr))

#define MMA_F16(d, a, b)                                                      \
    asm volatile(                                                             \
        "mma.sync.aligned.m16n8k16.row.col.f32.f16.f16.f32 "                  \
        "{%0,%1,%2,%3}, {%4,%5,%6,%7}, {%8,%9}, {%0,%1,%2,%3};\n"             \
        : "+f"((d)[0]), "+f"((d)[1]), "+f"((d)[2]), "+f"((d)[3])              \
        : "r"((a)[0]), "r"((a)[1]), "r"((a)[2]), "r"((a)[3]),                 \
          "r"((b)[0]), "r"((b)[1]))

// ---------------------------------------------------------------------------
// GEMM: C[M,N] = A[M,K] @ B[N,K]^T, fp32 accum, single-pass fp16, 3-stage.
// 256 threads, 8 warps as 4x2 grid of 64x64 warp tiles; CTA tile 256x128.
// AI from L2 = 85 FLOP/B (vs 64 at 128x128) -> below the LTS-cap roofline.
// EPI: 2 = fp16 out + bias; 3 = fp16 exp(BETA*acc) + atomic row sums;
//      4 = fp32 out / rsum[row].
// Grid (N/128, M/256, z).
// ---------------------------------------------------------------------------
template <int EPI>
__global__ void __launch_bounds__(256) gemm_s(
    const __half* __restrict__ A, long sA,
    const __half* __restrict__ B, long sB,
    const float* __restrict__ bias, int biasStride,
    float* __restrict__ rsum,
    float* __restrict__ C, __half* __restrict__ Ch,
    long sC, int K, int ldc)
{
    extern __shared__ __align__(128) char smem[];
    const uint32_t sb0 = s2u(smem);

    const int t = threadIdx.x;
    const int lane = t & 31;
    const int warp = t >> 5;
    const int wm = warp >> 1;            // 0..3 -> 64-row block
    const int wn = warp & 1;             // 0..1 -> 64-col block
    const int bz = blockIdx.z;

    const size_t aBase = (size_t)bz * sA + (size_t)blockIdx.y * 256 * K;
    const size_t bBase = (size_t)bz * sB + (size_t)blockIdx.x * 128 * K;

    // ldmatrix lane constants (proven mapping)
    const int m4 = lane >> 3;
    const int rA = ((m4 & 1) << 3) + (lane & 7);
    const int kA = (m4 >> 1) << 4;
    const int rB = ((m4 >> 1) << 3) + (lane & 7);
    const int kB = (m4 & 1) << 4;

    auto load_stage = [&](int st, int k0) {
        const uint32_t so = sb0 + st * STAGE_B;
#pragma unroll
        for (int i = 0; i < 6; i++) {
            int id = t + i * 256;            // 1536 ids: 1024 A + 512 B chunks
            if (id < 1024) {                 // A: 256 rows x 4 16B chunks
                int row = id >> 2;
                int c4 = id & 3;
                uint32_t sw = row * RSTRIDE + c4 * 16;
                cp16(so + sw, A + aBase + (size_t)row * K + k0 + c4 * 8);
            } else {                         // B: 128 rows x 4 16B chunks
                int id2 = id - 1024;
                int row = id2 >> 2;
                int c4 = id2 & 3;
                uint32_t sw = TILE_A + row * RSTRIDE + c4 * 16;
                cp16(so + sw, B + bBase + (size_t)row * K + k0 + c4 * 8);
            }
        }
        asm volatile("cp.async.commit_group;" ::: "memory");
    };

    float acc[4][8][4] = {};
    const int nk = K / KC;
    load_stage(0, 0);
    load_stage(1, KC);

    for (int kt = 0; kt < nk; kt++) {
        asm volatile("cp.async.wait_group 1;" ::: "memory");
        __syncthreads();
        if (kt + 2 < nk) load_stage((kt + 2) % NSTAGE, (kt + 2) * KC);

        const uint32_t st = sb0 + (kt % NSTAGE) * STAGE_B;
#pragma unroll
        for (int s = 0; s < 2; s++) {            // two k16 steps per chunk
            const int kb = s * 32;
            uint32_t ah[4][4], bh[4][4];
#pragma unroll
            for (int mi = 0; mi < 4; mi++) {
                int row = wm * 64 + mi * 16 + rA;
                LDSM4(ah[mi], st + row * RSTRIDE + kb + kA);
            }
#pragma unroll
            for (int nt = 0; nt < 4; nt++) {
                int row = wn * 64 + nt * 16 + rB;
                LDSM4(bh[nt], st + TILE_A + row * RSTRIDE + kb + kB);
            }
#pragma unroll
            for (int mi = 0; mi < 4; mi++)
#pragma unroll
                for (int ni = 0; ni < 8; ni++) {
                    const uint32_t* bp = &bh[ni >> 1][(ni & 1) * 2];
                    MMA_F16(acc[mi][ni], ah[mi], bp);
                }
        }
    }

    // Epilogue: warp owns 64 rows x 64 cols
    const int r = lane >> 2;
    const int cq = lane & 3;
    const int row0 = blockIdx.y * 256 + wm * 64;
    const int col0 = blockIdx.x * 128 + wn * 64;
    const size_t zC = (size_t)bz * sC;

#pragma unroll
    for (int mi = 0; mi < 4; mi++) {
        const int rr = row0 + mi * 16 + r;
        float inv0 = 0.f, inv1 = 0.f;
        if (EPI == 4) {
            inv0 = 1.0f / rsum[bz * SEQ + rr];
            inv1 = 1.0f / rsum[bz * SEQ + rr + 8];
        }
        float e0 = 0.f, e1 = 0.f;   // EPI==3 row partial sums
#pragma unroll
        for (int ni = 0; ni < 8; ni++) {
            int cc = col0 + ni * 8 + 2 * cq;
            if (EPI == 2) {
                float b0 = bias[bz * biasStride + cc];
                float b1 = bias[bz * biasStride + cc + 1];
                __half2 h0, h1;
                h0.x = __float2half(acc[mi][ni][0] + b0);
                h0.y = __float2half(acc[mi][ni][1] + b1);
                h1.x = __float2half(acc[mi][ni][2] + b0);
                h1.y = __float2half(acc[mi][ni][3] + b1);
                *(__half2*)(Ch + zC + (size_t)rr * ldc + cc) = h0;
                *(__half2*)(Ch + zC + (size_t)(rr + 8) * ldc + cc) = h1;
            } else if (EPI == 3) {
                float x0 = exp2f(acc[mi][ni][0] * BLOG2E);
                float x1 = exp2f(acc[mi][ni][1] * BLOG2E);
                float x2 = exp2f(acc[mi][ni][2] * BLOG2E);
                float x3 = exp2f(acc[mi][ni][3] * BLOG2E);
                e0 += x0 + x1;
                e1 += x2 + x3;
                __half2 h0, h1;
                h0.x = __float2half(x0); h0.y = __float2half(x1);
                h1.x = __float2half(x2); h1.y = __float2half(x3);
                *(__half2*)(Ch + zC + (size_t)rr * ldc + cc) = h0;
                *(__half2*)(Ch + zC + (size_t)(rr + 8) * ldc + cc) = h1;
            } else {  // EPI == 4
                float* Cp = C + zC;
                float2 v0 = make_float2(acc[mi][ni][0] * inv0, acc[mi][ni][1] * inv0);
                float2 v1 = make_float2(acc[mi][ni][2] * inv1, acc[mi][ni][3] * inv1);
                *(float2*)(Cp + (size_t)rr * ldc + cc) = v0;
                *(float2*)(Cp + (size_t)(rr + 8) * ldc + cc) = v1;
            }
        }
        if (EPI == 3) {
            e0 += __shfl_xor_sync(0xffffffff, e0, 1);
            e0 += __shfl_xor_sync(0xffffffff, e0, 2);
            e1 += __shfl_xor_sync(0xffffffff, e1, 1);
            e1 += __shfl_xor_sync(0xffffffff, e1, 2);
            if (cq == 0) {
                atomicAdd(&rsum[bz * SEQ + rr], e0);
                atomicAdd(&rsum[bz * SEQ + rr + 8], e1);
            }
        }
    }
}

// ---------------------------------------------------------------------------
// Batched elementwise convert: up to 3 fp32 sources -> fp16 (z picks source)
// ---------------------------------------------------------------------------
__global__ void __launch_bounds__(256) cvt3(
    const float* __restrict__ s0, const float* __restrict__ s1,
    const float* __restrict__ s2, __half* __restrict__ dst, int n4each)
{
    const int z = blockIdx.z;
    const float* x = (z == 0) ? s0 : (z == 1) ? s1 : s2;
    int i = blockIdx.x * 256 + threadIdx.x;
    if (i >= n4each) return;
    float4 v = ((const float4*)x)[i];
    __half2 h0, h1;
    h0.x = __float2half(v.x); h0.y = __float2half(v.y);
    h1.x = __float2half(v.z); h1.y = __float2half(v.w);
    size_t base = (size_t)z * n4each * 2;
    ((__half2*)dst)[base + 2 * i]     = h0;
    ((__half2*)dst)[base + 2 * i + 1] = h1;
}

// ---------------------------------------------------------------------------
// Batched convert + transpose: W_z[R][C] fp32 -> fp16 [z][C][R]
// ---------------------------------------------------------------------------
__global__ void __launch_bounds__(256) wcvtT3(
    const float* __restrict__ s0, const float* __restrict__ s1,
    const float* __restrict__ s2, __half* __restrict__ dst, int R, int Ccols)
{
    __shared__ float tile[32][33];
    const int z = blockIdx.z;
    const float* xp = (z == 0) ? s0 : (z == 1) ? s1 : s2;
    const size_t zo = (size_t)z * R * Ccols;
    const int c0 = blockIdx.x * 32, r0 = blockIdx.y * 32;
    const int tx = threadIdx.x, ty = threadIdx.y;
#pragma unroll
    for (int i = 0; i < 32; i += 8)
        tile[ty + i][tx] = xp[(size_t)(r0 + ty + i) * Ccols + c0 + tx];
    __syncthreads();
#pragma unroll
    for (int i = 0; i < 32; i += 8) {
        size_t o = zo + (size_t)(c0 + ty + i) * R + r0 + tx;
        dst[o] = __float2half(tile[tx][ty + i]);
    }
}

// ---------------------------------------------------------------------------
// fp16 transpose: v[z][S][D] -> vt[z][D][S]
// ---------------------------------------------------------------------------
__global__ void __launch_bounds__(256) vtransT(
    const __half* __restrict__ v, __half* __restrict__ vt)
{
    __shared__ __half th[32][33];
    const int z = blockIdx.z;
    const int c0 = blockIdx.x * 32, r0 = blockIdx.y * 32;
    const int tx = threadIdx.x, ty = threadIdx.y;
    const size_t inz = (size_t)z * SEQ * DIM;
#pragma unroll
    for (int i = 0; i < 32; i += 8)
        th[ty + i][tx] = v[inz + (size_t)(r0 + ty + i) * DIM + c0 + tx];
    __syncthreads();
#pragma unroll
    for (int i = 0; i < 32; i += 8)
        vt[inz + (size_t)(c0 + ty + i) * SEQ + r0 + tx] = th[tx][ty + i];
}

// ---------------------------------------------------------------------------
// Launch: QK chain on default stream; V branch forked onto s2, joined at AV.
// ---------------------------------------------------------------------------
extern "C" void kernel_launch(void* const* d_in, const int* in_sizes, int n_in,
                              void* d_out, int out_size)
{
    const float* query = (const float*)d_in[0];
    const float* key   = (const float*)d_in[1];
    const float* value = (const float*)d_in[2];
    const float* Wq    = (const float*)d_in[3];
    const float* bq    = (const float*)d_in[4];
    const float* Wk    = (const float*)d_in[5];
    const float* bk    = (const float*)d_in[6];
    const float* Wv    = (const float*)d_in[7];
    const float* bv    = (const float*)d_in[8];
    float* out = (float*)d_out;

    __half *x, *w, *qkv, *vt, *pp;
    float *bias, *rsum;
    cudaGetSymbolAddress((void**)&x, g_x);
    cudaGetSymbolAddress((void**)&w, g_w);
    cudaGetSymbolAddress((void**)&bias, g_bias);
    cudaGetSymbolAddress((void**)&qkv, g_qkv);
    cudaGetSymbolAddress((void**)&vt, g_vt);
    cudaGetSymbolAddress((void**)&pp, g_p);
    cudaGetSymbolAddress((void**)&rsum, g_rsum);

    cudaFuncSetAttribute((const void*)gemm_s<2>,
                         cudaFuncAttributeMaxDynamicSharedMemorySize, SMEM_TOTAL);
    cudaFuncSetAttribute((const void*)gemm_s<3>,
                         cudaFuncAttributeMaxDynamicSharedMemorySize, SMEM_TOTAL);
    cudaFuncSetAttribute((const void*)gemm_s<4>,
                         cudaFuncAttributeMaxDynamicSharedMemorySize, SMEM_TOTAL);

    // One-time infra (created before any capture on the correctness call;
    // no device memory involved). Work per call is identical.
    static cudaStream_t s2 = nullptr;
    static cudaEvent_t evF = nullptr, evJ = nullptr;
    if (!s2) {
        cudaStreamCreateWithFlags(&s2, cudaStreamNonBlocking);
        cudaEventCreateWithFlags(&evF, cudaEventDisableTiming);
        cudaEventCreateWithFlags(&evJ, cudaEventDisableTiming);
    }

    const long PD = (long)MTOT * DIM;     // per-z projection stride
    const long WD = (long)DIM * DIM;
    const int nIn4 = MTOT * DIM / 4;

    // ---- Fork: V branch onto s2 ----
    cudaEventRecord(evF, 0);
    cudaStreamWaitEvent(s2, evF, 0);

    // ---- Main stream: QK chain ----
    cudaMemcpyAsync(bias,       bq, DIM * sizeof(float), cudaMemcpyDeviceToDevice);
    cudaMemcpyAsync(bias + DIM, bk, DIM * sizeof(float), cudaMemcpyDeviceToDevice);
    cudaMemsetAsync(rsum, 0, MTOT * sizeof(float));
    cvt3<<<dim3(nIn4 / 256, 1, 2), 256>>>(query, key, key, x, nIn4);
    wcvtT3<<<dim3(DIM / 32, DIM / 32, 2), dim3(32, 8)>>>(Wq, Wk, Wk, w, DIM, DIM);
    gemm_s<2><<<dim3(DIM / 128, MTOT / 256, 2), 256, SMEM_TOTAL>>>(
        x, PD, w, WD, bias, DIM, nullptr, nullptr, qkv, PD, DIM, DIM);
    // Scores + fused exp + atomic row sums
    gemm_s<3><<<dim3(SEQ / 128, SEQ / 256, BATCH), 256, SMEM_TOTAL>>>(
        qkv, (long)SEQ * DIM, qkv + PD, (long)SEQ * DIM,
        nullptr, 0, rsum, nullptr, pp, (long)SEQ * SEQ, DIM, SEQ);

    // ---- s2: V branch (independent of QK chain) ----
    cudaMemcpyAsync(bias + 2 * DIM, bv, DIM * sizeof(float),
                    cudaMemcpyDeviceToDevice, s2);
    cvt3<<<dim3(nIn4 / 256, 1, 1), 256, 0, s2>>>(value, value, value,
                                                 x + 2 * PD, nIn4);
    wcvtT3<<<dim3(DIM / 32, DIM / 32, 1), dim3(32, 8), 0, s2>>>(
        Wv, Wv, Wv, w + 2 * WD, DIM, DIM);
    gemm_s<2><<<dim3(DIM / 128, MTOT / 256, 1), 256, SMEM_TOTAL, s2>>>(
        x + 2 * PD, PD, w + 2 * WD, WD, bias + 2 * DIM, 0, nullptr,
        nullptr, qkv + 2 * PD, PD, DIM, DIM);
    vtransT<<<dim3(DIM / 32, SEQ / 32, BATCH), dim3(32, 8), 0, s2>>>(
        qkv + 2 * PD, vt);
    cudaEventRecord(evJ, s2);

    // ---- Join, then AV: (p @ v^T) / rsum ----
    cudaStreamWaitEvent(0, evJ, 0);
    gemm_s<4><<<dim3(DIM / 128, SEQ / 256, BATCH), 256, SMEM_TOTAL>>>(
        pp, (long)SEQ * SEQ, vt, (long)SEQ * DIM,
        nullptr, 0, rsum, out, nullptr, (long)SEQ * DIM, SEQ, DIM);
}

// round 16
// speedup vs baseline: 1.3183x; 1.3183x over previous
#include <cuda_runtime.h>
#include <cuda_fp16.h>
#include <stdint.h>
#include <math.h>

// Problem constants
#define BATCH 4
#define SEQ   2048
#define DIM   1024
#define MTOT  (BATCH * SEQ)      // 8192
#define BETA  0.03125f
#define BLOG2E 0.04508422f       // BETA * log2(e)

// GEMM tiling (R14-proven): 128x128 CTA tile, 4 warps (2x2 of 64x64), KC=32
#define KC       32
#define RSTRIDE  80                  // bytes per smem row (32 fp16 + 16B pad)
#define TILE_B   (128 * RSTRIDE)     // 10240 B
#define STAGE_B  (2 * TILE_B)        // A | B = 20480 B
#define NSTAGE   4
#define SMEM_TOTAL (NSTAGE * STAGE_B)  // 81920 B -> 2 CTAs/SM (160 KB of 228)

// ---------------------------------------------------------------------------
// Scratch (__device__ globals; allocation-free rule)
// ---------------------------------------------------------------------------
__device__ __align__(16) __half g_x[3 * MTOT * DIM];      // fp16 inputs
__device__ __align__(16) __half g_w[3 * DIM * DIM];       // fp16 weights (transposed)
__device__ __align__(16) float  g_bias[3 * DIM];
__device__ __align__(16) __half g_qkv[3 * MTOT * DIM];    // fp16 q,k,v
__device__ __align__(16) __half g_vt[MTOT * DIM];         // v transposed [z][D][S]
__device__ __align__(16) __half g_p[(size_t)BATCH * SEQ * SEQ];  // exp(beta*s)
__device__ __align__(16) float  g_rsum[MTOT];             // row sums (atomic)

// ---------------------------------------------------------------------------
// Helpers
// ---------------------------------------------------------------------------
__device__ __forceinline__ uint32_t s2u(const void* p) {
    return (uint32_t)__cvta_generic_to_shared(p);
}
__device__ __forceinline__ void cp16(uint32_t s, const void* g) {
    asm volatile("cp.async.cg.shared.global [%0], [%1], 16;" :: "r"(s), "l"(g));
}

#define LDSM4(r, addr)                                                        \
    asm volatile("ldmatrix.sync.aligned.m8n8.x4.shared.b16 {%0,%1,%2,%3}, [%4];" \
                 : "=r"((r)[0]), "=r"((r)[1]), "=r"((r)[2]), "=r"((r)[3])     \
                 : "r"(addr))

#define MMA_F16(d, a, b)                                                      \
    asm volatile(                                                             \
        "mma.sync.aligned.m16n8k16.row.col.f32.f16.f16.f32 "                  \
        "{%0,%1,%2,%3}, {%4,%5,%6,%7}, {%8,%9}, {%0,%1,%2,%3};\n"             \
        : "+f"((d)[0]), "+f"((d)[1]), "+f"((d)[2]), "+f"((d)[3])              \
        : "r"((a)[0]), "r"((a)[1]), "r"((a)[2]), "r"((a)[3]),                 \
          "r"((b)[0]), "r"((b)[1]))

// ---------------------------------------------------------------------------
// GEMM: C[M,N] = A[M,K] @ B[N,K]^T, fp32 accum, single-pass fp16, 4-stage.
// 128 threads, 4 warps as 2x2 grid of 64x64 warp tiles.
// Pipeline: prefetch distance 3, two load-groups in flight (wait_group 2),
// provably-correct tail drain (wait_group 0 once <2 younger groups exist).
// EPI: 2 = fp16 out + bias; 3 = fp16 exp(BETA*acc) + atomic row sums;
//      4 = fp32 out / rsum[row].
// Grid (N/128, M/128, z).
// ---------------------------------------------------------------------------
template <int EPI>
__global__ void __launch_bounds__(128) gemm_s(
    const __half* __restrict__ A, long sA,
    const __half* __restrict__ B, long sB,
    const float* __restrict__ bias, int biasStride,
    float* __restrict__ rsum,
    float* __restrict__ C, __half* __restrict__ Ch,
    long sC, int K, int ldc)
{
    extern __shared__ __align__(128) char smem[];
    const uint32_t sb0 = s2u(smem);

    const int t = threadIdx.x;
    const int lane = t & 31;
    const int warp = t >> 5;
    const int wm = warp >> 1;            // 0..1 -> 64-row block
    const int wn = warp & 1;             // 0..1 -> 64-col block
    const int bz = blockIdx.z;

    const size_t aBase = (size_t)bz * sA + (size_t)blockIdx.y * 128 * K;
    const size_t bBase = (size_t)bz * sB + (size_t)blockIdx.x * 128 * K;

    // ldmatrix lane constants (proven mapping)
    const int m4 = lane >> 3;
    const int rA = ((m4 & 1) << 3) + (lane & 7);
    const int kA = (m4 >> 1) << 4;
    const int rB = ((m4 >> 1) << 3) + (lane & 7);
    const int kB = (m4 & 1) << 4;

    auto load_stage = [&](int st, int k0) {
        const uint32_t so = sb0 + st * STAGE_B;
#pragma unroll
        for (int i = 0; i < 4; i++) {
            int id = t + i * 128;            // 512 ids = 128 rows x 4 16B chunks
            int row = id >> 2;
            int c4 = id & 3;
            uint32_t sw = row * RSTRIDE + c4 * 16;
            size_t ga = aBase + (size_t)row * K + k0 + c4 * 8;
            size_t gb = bBase + (size_t)row * K + k0 + c4 * 8;
            cp16(so + sw,          A + ga);
            cp16(so + TILE_B + sw, B + gb);
        }
        asm volatile("cp.async.commit_group;" ::: "memory");
    };

    float acc[4][8][4] = {};
    const int nk = K / KC;               // >= 32 for all call sites
    load_stage(0, 0);
    load_stage(1, KC);
    load_stage(2, 2 * KC);

    for (int kt = 0; kt < nk; kt++) {
        // Group kt must be complete. Groups younger than kt still issuable:
        // exactly 2 while kt+2 < nk, else drain fully (conservative, cheap).
        if (kt + 2 < nk) {
            asm volatile("cp.async.wait_group 2;" ::: "memory");
        } else {
            asm volatile("cp.async.wait_group 0;" ::: "memory");
        }
        __syncthreads();
        if (kt + 3 < nk) load_stage((kt + 3) % NSTAGE, (kt + 3) * KC);

        const uint32_t st = sb0 + (kt % NSTAGE) * STAGE_B;
#pragma unroll
        for (int s = 0; s < 2; s++) {            // two k16 steps per chunk
            const int kb = s * 32;
            uint32_t ah[4][4], bh[4][4];
#pragma unroll
            for (int mi = 0; mi < 4; mi++) {
                int row = wm * 64 + mi * 16 + rA;
                LDSM4(ah[mi], st + row * RSTRIDE + kb + kA);
            }
#pragma unroll
            for (int nt = 0; nt < 4; nt++) {
                int row = wn * 64 + nt * 16 + rB;
                LDSM4(bh[nt], st + TILE_B + row * RSTRIDE + kb + kB);
            }
#pragma unroll
            for (int mi = 0; mi < 4; mi++)
#pragma unroll
                for (int ni = 0; ni < 8; ni++) {
                    const uint32_t* bp = &bh[ni >> 1][(ni & 1) * 2];
                    MMA_F16(acc[mi][ni], ah[mi], bp);
                }
        }
    }

    // Epilogue: warp owns 64 rows x 64 cols
    const int r = lane >> 2;
    const int cq = lane & 3;
    const int row0 = blockIdx.y * 128 + wm * 64;
    const int col0 = blockIdx.x * 128 + wn * 64;
    const size_t zC = (size_t)bz * sC;

#pragma unroll
    for (int mi = 0; mi < 4; mi++) {
        const int rr = row0 + mi * 16 + r;
        float inv0 = 0.f, inv1 = 0.f;
        if (EPI == 4) {
            inv0 = 1.0f / rsum[bz * SEQ + rr];
            inv1 = 1.0f / rsum[bz * SEQ + rr + 8];
        }
        float e0 = 0.f, e1 = 0.f;   // EPI==3 row partial sums
#pragma unroll
        for (int ni = 0; ni < 8; ni++) {
            int cc = col0 + ni * 8 + 2 * cq;
            if (EPI == 2) {
                float b0 = bias[bz * biasStride + cc];
                float b1 = bias[bz * biasStride + cc + 1];
                __half2 h0, h1;
                h0.x = __float2half(acc[mi][ni][0] + b0);
                h0.y = __float2half(acc[mi][ni][1] + b1);
                h1.x = __float2half(acc[mi][ni][2] + b0);
                h1.y = __float2half(acc[mi][ni][3] + b1);
                *(__half2*)(Ch + zC + (size_t)rr * ldc + cc) = h0;
                *(__half2*)(Ch + zC + (size_t)(rr + 8) * ldc + cc) = h1;
            } else if (EPI == 3) {
                float x0 = exp2f(acc[mi][ni][0] * BLOG2E);
                float x1 = exp2f(acc[mi][ni][1] * BLOG2E);
                float x2 = exp2f(acc[mi][ni][2] * BLOG2E);
                float x3 = exp2f(acc[mi][ni][3] * BLOG2E);
                e0 += x0 + x1;
                e1 += x2 + x3;
                __half2 h0, h1;
                h0.x = __float2half(x0); h0.y = __float2half(x1);
                h1.x = __float2half(x2); h1.y = __float2half(x3);
                *(__half2*)(Ch + zC + (size_t)rr * ldc + cc) = h0;
                *(__half2*)(Ch + zC + (size_t)(rr + 8) * ldc + cc) = h1;
            } else {  // EPI == 4
                float* Cp = C + zC;
                float2 v0 = make_float2(acc[mi][ni][0] * inv0, acc[mi][ni][1] * inv0);
                float2 v1 = make_float2(acc[mi][ni][2] * inv1, acc[mi][ni][3] * inv1);
                *(float2*)(Cp + (size_t)rr * ldc + cc) = v0;
                *(float2*)(Cp + (size_t)(rr + 8) * ldc + cc) = v1;
            }
        }
        if (EPI == 3) {
            e0 += __shfl_xor_sync(0xffffffff, e0, 1);
            e0 += __shfl_xor_sync(0xffffffff, e0, 2);
            e1 += __shfl_xor_sync(0xffffffff, e1, 1);
            e1 += __shfl_xor_sync(0xffffffff, e1, 2);
            if (cq == 0) {
                atomicAdd(&rsum[bz * SEQ + rr], e0);
                atomicAdd(&rsum[bz * SEQ + rr + 8], e1);
            }
        }
    }
}

// ---------------------------------------------------------------------------
// Batched elementwise convert: up to 3 fp32 sources -> fp16 (z picks source)
// ---------------------------------------------------------------------------
__global__ void __launch_bounds__(256) cvt3(
    const float* __restrict__ s0, const float* __restrict__ s1,
    const float* __restrict__ s2, __half* __restrict__ dst, int n4each)
{
    const int z = blockIdx.z;
    const float* x = (z == 0) ? s0 : (z == 1) ? s1 : s2;
    int i = blockIdx.x * 256 + threadIdx.x;
    if (i >= n4each) return;
    float4 v = ((const float4*)x)[i];
    __half2 h0, h1;
    h0.x = __float2half(v.x); h0.y = __float2half(v.y);
    h1.x = __float2half(v.z); h1.y = __float2half(v.w);
    size_t base = (size_t)z * n4each * 2;
    ((__half2*)dst)[base + 2 * i]     = h0;
    ((__half2*)dst)[base + 2 * i + 1] = h1;
}

// ---------------------------------------------------------------------------
// Batched convert + transpose: W_z[R][C] fp32 -> fp16 [z][C][R]
// ---------------------------------------------------------------------------
__global__ void __launch_bounds__(256) wcvtT3(
    const float* __restrict__ s0, const float* __restrict__ s1,
    const float* __restrict__ s2, __half* __restrict__ dst, int R, int Ccols)
{
    __shared__ float tile[32][33];
    const int z = blockIdx.z;
    const float* xp = (z == 0) ? s0 : (z == 1) ? s1 : s2;
    const size_t zo = (size_t)z * R * Ccols;
    const int c0 = blockIdx.x * 32, r0 = blockIdx.y * 32;
    const int tx = threadIdx.x, ty = threadIdx.y;
#pragma unroll
    for (int i = 0; i < 32; i += 8)
        tile[ty + i][tx] = xp[(size_t)(r0 + ty + i) * Ccols + c0 + tx];
    __syncthreads();
#pragma unroll
    for (int i = 0; i < 32; i += 8) {
        size_t o = zo + (size_t)(c0 + ty + i) * R + r0 + tx;
        dst[o] = __float2half(tile[tx][ty + i]);
    }
}

// ---------------------------------------------------------------------------
// fp16 transpose: v[z][S][D] -> vt[z][D][S]
// ---------------------------------------------------------------------------
__global__ void __launch_bounds__(256) vtransT(
    const __half* __restrict__ v, __half* __restrict__ vt)
{
    __shared__ __half th[32][33];
    const int z = blockIdx.z;
    const int c0 = blockIdx.x * 32, r0 = blockIdx.y * 32;
    const int tx = threadIdx.x, ty = threadIdx.y;
    const size_t inz = (size_t)z * SEQ * DIM;
#pragma unroll
    for (int i = 0; i < 32; i += 8)
        th[ty + i][tx] = v[inz + (size_t)(r0 + ty + i) * DIM + c0 + tx];
    __syncthreads();
#pragma unroll
    for (int i = 0; i < 32; i += 8)
        vt[inz + (size_t)(c0 + ty + i) * SEQ + r0 + tx] = th[tx][ty + i];
}

// ---------------------------------------------------------------------------
// Launch: QK chain on default stream; V branch forked onto s2, joined at AV.
// ---------------------------------------------------------------------------
extern "C" void kernel_launch(void* const* d_in, const int* in_sizes, int n_in,
                              void* d_out, int out_size)
{
    const float* query = (const float*)d_in[0];
    const float* key   = (const float*)d_in[1];
    const float* value = (const float*)d_in[2];
    const float* Wq    = (const float*)d_in[3];
    const float* bq    = (const float*)d_in[4];
    const float* Wk    = (const float*)d_in[5];
    const float* bk    = (const float*)d_in[6];
    const float* Wv    = (const float*)d_in[7];
    const float* bv    = (const float*)d_in[8];
    float* out = (float*)d_out;

    __half *x, *w, *qkv, *vt, *pp;
    float *bias, *rsum;
    cudaGetSymbolAddress((void**)&x, g_x);
    cudaGetSymbolAddress((void**)&w, g_w);
    cudaGetSymbolAddress((void**)&bias, g_bias);
    cudaGetSymbolAddress((void**)&qkv, g_qkv);
    cudaGetSymbolAddress((void**)&vt, g_vt);
    cudaGetSymbolAddress((void**)&pp, g_p);
    cudaGetSymbolAddress((void**)&rsum, g_rsum);

    cudaFuncSetAttribute((const void*)gemm_s<2>,
                         cudaFuncAttributeMaxDynamicSharedMemorySize, SMEM_TOTAL);
    cudaFuncSetAttribute((const void*)gemm_s<3>,
                         cudaFuncAttributeMaxDynamicSharedMemorySize, SMEM_TOTAL);
    cudaFuncSetAttribute((const void*)gemm_s<4>,
                         cudaFuncAttributeMaxDynamicSharedMemorySize, SMEM_TOTAL);

    // One-time infra (created before any capture on the correctness call;
    // no device memory involved). Work per call is identical.
    static cudaStream_t s2 = nullptr;
    static cudaEvent_t evF = nullptr, evJ = nullptr;
    if (!s2) {
        cudaStreamCreateWithFlags(&s2, cudaStreamNonBlocking);
        cudaEventCreateWithFlags(&evF, cudaEventDisableTiming);
        cudaEventCreateWithFlags(&evJ, cudaEventDisableTiming);
    }

    const long PD = (long)MTOT * DIM;     // per-z projection stride
    const long WD = (long)DIM * DIM;
    const int nIn4 = MTOT * DIM / 4;

    // ---- Fork: V branch onto s2 ----
    cudaEventRecord(evF, 0);
    cudaStreamWaitEvent(s2, evF, 0);

    // ---- Main stream: QK chain ----
    cudaMemcpyAsync(bias,       bq, DIM * sizeof(float), cudaMemcpyDeviceToDevice);
    cudaMemcpyAsync(bias + DIM, bk, DIM * sizeof(float), cudaMemcpyDeviceToDevice);
    cudaMemsetAsync(rsum, 0, MTOT * sizeof(float));
    cvt3<<<dim3(nIn4 / 256, 1, 2), 256>>>(query, key, key, x, nIn4);
    wcvtT3<<<dim3(DIM / 32, DIM / 32, 2), dim3(32, 8)>>>(Wq, Wk, Wk, w, DIM, DIM);
    gemm_s<2><<<dim3(DIM / 128, MTOT / 128, 2), 128, SMEM_TOTAL>>>(
        x, PD, w, WD, bias, DIM, nullptr, nullptr, qkv, PD, DIM, DIM);
    // Scores + fused exp + atomic row sums
    gemm_s<3><<<dim3(SEQ / 128, SEQ / 128, BATCH), 128, SMEM_TOTAL>>>(
        qkv, (long)SEQ * DIM, qkv + PD, (long)SEQ * DIM,
        nullptr, 0, rsum, nullptr, pp, (long)SEQ * SEQ, DIM, SEQ);

    // ---- s2: V branch (independent of QK chain) ----
    cudaMemcpyAsync(bias + 2 * DIM, bv, DIM * sizeof(float),
                    cudaMemcpyDeviceToDevice, s2);
    cvt3<<<dim3(nIn4 / 256, 1, 1), 256, 0, s2>>>(value, value, value,
                                                 x + 2 * PD, nIn4);
    wcvtT3<<<dim3(DIM / 32, DIM / 32, 1), dim3(32, 8), 0, s2>>>(
        Wv, Wv, Wv, w + 2 * WD, DIM, DIM);
    gemm_s<2><<<dim3(DIM / 128, MTOT / 128, 1), 128, SMEM_TOTAL, s2>>>(
        x + 2 * PD, PD, w + 2 * WD, WD, bias + 2 * DIM, 0, nullptr,
        nullptr, qkv + 2 * PD, PD, DIM, DIM);
    vtransT<<<dim3(DIM / 32, SEQ / 32, BATCH), dim3(32, 8), 0, s2>>>(
        qkv + 2 * PD, vt);
    cudaEventRecord(evJ, s2);

    // ---- Join, then AV: (p @ v^T) / rsum ----
    cudaStreamWaitEvent(0, evJ, 0);
    gemm_s<4><<<dim3(DIM / 128, SEQ / 128, BATCH), 128, SMEM_TOTAL>>>(
        pp, (long)SEQ * SEQ, vt, (long)SEQ * DIM,
        nullptr, 0, rsum, out, nullptr, (long)SEQ * DIM, SEQ, DIM);
}